// round 12
// baseline (speedup 1.0000x reference)
#include <cuda_runtime.h>

#define NB   512
#define NC   16
#define NT   2000
#define NRES 1024
#define NCLS 10
#define NBLK 148
#define NTHR 512
#define ALPHA 0.9f

// Persistent cross-CTA state.
__device__ float g_s [2][NB * NRES];   // spikes, [b][j] (classifier layout)
__device__ float g_sT[2][NRES * NB];   // spikes, [k][b] (GEMM A layout)
__device__ float g_WresT[NRES * NRES]; // Wres^T, [k][j]
__device__ float g_xT[(size_t)NT * NB * NC];  // x^T: [t][b][c]
__device__ unsigned g_bar_count;
__device__ unsigned g_bar_gen;

static __device__ __forceinline__ unsigned ld_acq(const unsigned* p) {
    unsigned v;
    asm volatile("ld.acquire.gpu.global.u32 %0, [%1];" : "=r"(v) : "l"(p) : "memory");
    return v;
}
static __device__ __forceinline__ void st_rel(unsigned* p, unsigned v) {
    asm volatile("st.release.gpu.global.u32 [%0], %1;" :: "l"(p), "r"(v) : "memory");
}

// Grid-wide barrier; all 148 CTAs resident (1 per SM).
static __device__ __forceinline__ void grid_barrier() {
    __syncthreads();
    if (threadIdx.x == 0) {
        unsigned gen = ld_acq(&g_bar_gen);
        __threadfence();
        if (atomicAdd(&g_bar_count, 1u) == NBLK - 1u) {
            g_bar_count = 0u;
            __threadfence();
            st_rel(&g_bar_gen, gen + 1u);
        } else {
            while (ld_acq(&g_bar_gen) == gen) { }
        }
    }
    __syncthreads();
}

// fma.rn.f32x2: two independent rn fp32 FMAs — per-lane bit-identical.
static __device__ __forceinline__ unsigned long long pack2(float lo, float hi) {
    unsigned long long r;
    asm("mov.b64 %0, {%1, %2};" : "=l"(r) : "f"(lo), "f"(hi));
    return r;
}
static __device__ __forceinline__ void unpack2(unsigned long long p, float& lo, float& hi) {
    asm("mov.b64 {%0, %1}, %2;" : "=f"(lo), "=f"(hi) : "l"(p));
}
static __device__ __forceinline__ void fma2(unsigned long long& acc,
                                            unsigned long long a,
                                            unsigned long long b) {
    asm("fma.rn.f32x2 %0, %1, %2, %0;" : "+l"(acc) : "l"(a), "l"(b));
}

// cp.async 16B global->shared, commit/wait.
static __device__ __forceinline__ void cp16(unsigned dst_smem, const void* src) {
    asm volatile("cp.async.cg.shared.global [%0], [%1], 16;"
                 :: "r"(dst_smem), "l"(src) : "memory");
}
static __device__ __forceinline__ void cp_commit() {
    asm volatile("cp.async.commit_group;" ::: "memory");
}
static __device__ __forceinline__ void cp_wait0() {
    asm volatile("cp.async.wait_group 0;" ::: "memory");
}

__global__ __launch_bounds__(NTHR, 1) void reservoir_persistent(
    const float* __restrict__ x,     // (NB, NC, NT)
    const float* __restrict__ Win,   // (NRES, NC)
    const float* __restrict__ Wres,  // (NRES, NRES)
    const float* __restrict__ Wclf,  // (NCLS, NRES)
    float* __restrict__ out)         // [NB*NCLS | NB*NRES]
{
    const int blk = blockIdx.x;
    const int tid = threadIdx.x;

    // Double-buffered staging pool: buf{0,1} x (As[32][68], Bs[32][68]).
    // Epilogue aliases the first 64x68 floats as spt.
    __shared__ __align__(16) float pool[2 * 64 * 68];
    __shared__ float sx[64][17];
    __shared__ float sWin[64][17];

    // ---- Phase 0 (all CTAs): one-time transposes ----
    {
        const int g0 = blk * NTHR + tid;
        const int gs = NBLK * NTHR;
        for (int i = g0; i < NRES * NRES; i += gs) {
            int j = i >> 10, k = i & (NRES - 1);
            g_WresT[k * NRES + j] = Wres[i];
        }
        for (size_t i = g0; i < (size_t)NT * NB * NC; i += (size_t)gs) {
            int t = (int)(i >> 13);           // NB*NC = 8192
            int r = (int)(i & 8191);
            int b = r >> 4, c = r & 15;
            g_xT[i] = x[((size_t)(b * NC + c)) * NT + t];
        }
    }

    if (blk < 128) {
        // ---------------- Reservoir path (512 threads, 16 warps) -------------
        const int b0 = (blk >> 4) * 64;
        const int j0 = (blk & 15) * 64;

        // Thread tile 2b x 4j. Warp = 8b x 32j; 16 warps = 8(b) x 2(j).
        const int w    = tid >> 5;
        const int lane = tid & 31;
        const int rl0 = (w >> 1) * 8 + (lane >> 3) * 2;   // CTA-local row (2 rows)
        const int cl0 = (w & 1) * 32 + (lane & 7) * 4;    // CTA-local col (4 cols)

        // Staging decode: 512 threads cover a 32k x 64 tile with one cp16 each.
        const int kq = tid >> 4;          // 0..31
        const int qq = tid & 15;          // 0..15

        const unsigned pool_u = (unsigned)__cvta_generic_to_shared(pool);
        const unsigned bufBytes = 64 * 68 * 4;
        const unsigned dA = pool_u + ((kq)      * 68 + qq * 4) * 4;
        const unsigned dB = pool_u + ((32 + kq) * 68 + qq * 4) * 4;

        // Zero step-0 spikes (both layouts).
        {
            float4 z = make_float4(0.f, 0.f, 0.f, 0.f);
#pragma unroll
            for (int i = 0; i < 2; i++)
                __stcg((float4*)&g_s[0][(size_t)(b0 + rl0 + i) * NRES + j0 + cl0], z);
            for (int e = tid; e < 64 * 16; e += NTHR) {
                int jl = e >> 4, bq = e & 15;
                __stcg((float4*)&g_sT[0][(size_t)(j0 + jl) * NB + b0 + bq * 4], z);
            }
        }
        for (int e = tid; e < 64 * 16; e += NTHR) {
            int r = e >> 4, c = e & 15;
            sWin[r][c] = Win[(size_t)(j0 + r) * NC + c];
        }

        float v[8], cnt[8];
#pragma unroll
        for (int q = 0; q < 8; q++) { v[q] = 0.f; cnt[q] = 0.f; }

        grid_barrier();

        for (int t = 0; t < NT; ++t) {
            const float* __restrict__ sTprev = g_sT[t & 1];
            float* __restrict__ s_next  = g_s [(t + 1) & 1];
            float* __restrict__ sT_next = g_sT[(t + 1) & 1];

            // Stage x_t tile (coalesced).
            {
                const float* xt = &g_xT[(size_t)t * (NB * NC) + (size_t)b0 * NC];
                for (int e = tid; e < 64 * 16; e += NTHR)
                    sx[e >> 4][e & 15] = xt[e];
            }

            unsigned long long acc2[2][2];
#pragma unroll
            for (int i = 0; i < 2; i++) {
                acc2[i][0] = pack2(0.f, 0.f);
                acc2[i][1] = pack2(0.f, 0.f);
            }

            // Prologue: async-stage chunk 31 into buf 1.
            {
                const int kg = 31 * 32;
                cp16(dA + bufBytes, &sTprev [(size_t)(kg + kq) * NB   + b0 + qq * 4]);
                cp16(dB + bufBytes, &g_WresT[(size_t)(kg + kq) * NRES + j0 + qq * 4]);
                cp_commit();
            }

            for (int kc = 31; kc >= 0; --kc) {
                cp_wait0();
                __syncthreads();

                if (kc > 0) {
                    const int kg = (kc - 1) * 32;
                    const unsigned off = ((kc - 1) & 1) * bufBytes;
                    cp16(dA + off, &sTprev [(size_t)(kg + kq) * NB   + b0 + qq * 4]);
                    cp16(dB + off, &g_WresT[(size_t)(kg + kq) * NRES + j0 + qq * 4]);
                    cp_commit();
                }

                const unsigned base = pool_u + (kc & 1) * bufBytes;
                const unsigned aAddr0 = base + rl0 * 4;
                const unsigned bAddr0 = base + (32 * 68 + cl0) * 4;
#pragma unroll
                for (int k = 31; k >= 0; --k) {
                    float a0, a1;
                    asm("ld.shared.v2.f32 {%0, %1}, [%2];"
                        : "=f"(a0), "=f"(a1) : "r"(aAddr0 + k * 68 * 4));
                    unsigned long long b01, b23;
                    asm("ld.shared.v2.u64 {%0, %1}, [%2];"
                        : "=l"(b01), "=l"(b23) : "r"(bAddr0 + k * 68 * 4));
                    unsigned long long a00 = pack2(a0, a0);
                    unsigned long long a11 = pack2(a1, a1);
                    fma2(acc2[0][0], a00, b01);
                    fma2(acc2[0][1], a00, b23);
                    fma2(acc2[1][0], a11, b01);
                    fma2(acc2[1][1], a11, b23);
                }
            }

            float acc[2][4];
#pragma unroll
            for (int i = 0; i < 2; i++) {
                unpack2(acc2[i][0], acc[i][0], acc[i][1]);
                unpack2(acc2[i][1], acc[i][2], acc[i][3]);
            }

            __syncthreads();   // mainloop reads done; pool reused as spt

            // Epilogue (frozen): vn = rn(fma(0.9, v, d_in) + d_rec)
            float (*spt)[68] = (float(*)[68])pool;   // [j_local][b_local]
#pragma unroll
            for (int i = 0; i < 2; i++) {
                const int rb = rl0 + i;
                float sp[4];
#pragma unroll
                for (int j = 0; j < 4; j++) {
                    const int cj = cl0 + j;
                    float d = 0.f;
#pragma unroll
                    for (int c = 0; c < NC; c++)
                        d = __fmaf_rn(sx[rb][c], sWin[cj][c], d);
                    const int q = i * 4 + j;
                    float vn = __fadd_rn(__fmaf_rn(ALPHA, v[q], d), acc[i][j]);
                    float s = (vn >= 1.0f) ? 1.0f : 0.0f;
                    v[q] = (vn >= 1.0f) ? 0.0f : vn;
                    cnt[q] += s;
                    sp[j] = s;
                    spt[cj][rb] = s;
                }
                __stcg((float4*)&s_next[(size_t)(b0 + rb) * NRES + j0 + cl0],
                       make_float4(sp[0], sp[1], sp[2], sp[3]));
            }
            __syncthreads();
            for (int e = tid; e < 64 * 16; e += NTHR) {
                int jl = e >> 4, bq = e & 15;
                float4 val = *(const float4*)&spt[jl][bq * 4];
                __stcg((float4*)&sT_next[(size_t)(j0 + jl) * NB + b0 + bq * 4], val);
            }

            grid_barrier();
        }
        grid_barrier();   // classifier finishes step NT-1

#pragma unroll
        for (int i = 0; i < 2; i++) {
            *(float4*)&out[(size_t)NB * NCLS +
                           (size_t)(b0 + rl0 + i) * NRES + j0 + cl0] =
                make_float4(cnt[i * 4 + 0], cnt[i * 4 + 1], cnt[i * 4 + 2], cnt[i * 4 + 3]);
        }
    } else {
        // ---------------- Classifier path (tid<256 active; numerics frozen) --
        const bool active = tid < 256;
        const int idx = (blk - 128) * 256 + tid;   // 0..5119 when active
        const int b = idx / NCLS;
        const int m = idx % NCLS;
        float vc = 0.f, cc = 0.f;

        grid_barrier();

        for (int t = 0; t <= NT; ++t) {
            if (t >= 1 && active) {
                const float* __restrict__ s_prev = g_s[t & 1];  // spikes of step t-1
                const float* srow = &s_prev[(size_t)b * NRES];
                const float* wrow = &Wclf[(size_t)m * NRES];
                float tot = 0.f;
#pragma unroll
                for (int blkk = 0; blkk < 4; ++blkk) {
                    float a = 0.f;
#pragma unroll 8
                    for (int n = 0; n < 256; n += 4) {
                        int base = blkk * 256 + n;
                        float4 sv = __ldcg((const float4*)(srow + base));
                        float4 wv = *(const float4*)(wrow + base);
                        a = __fmaf_rn(sv.x, wv.x, a);
                        a = __fmaf_rn(sv.y, wv.y, a);
                        a = __fmaf_rn(sv.z, wv.z, a);
                        a = __fmaf_rn(sv.w, wv.w, a);
                    }
                    tot = __fadd_rn(tot, a);
                }
                float vn = __fmaf_rn(ALPHA, vc, tot);
                float s = (vn >= 1.0f) ? 1.0f : 0.0f;
                vc = (vn >= 1.0f) ? 0.0f : vn;
                cc += s;
            }
            grid_barrier();
        }
        if (active) out[idx] = cc;
    }
}

extern "C" void kernel_launch(void* const* d_in, const int* in_sizes, int n_in,
                              void* d_out, int out_size) {
    const float* x = 0; const float* Win = 0;
    const float* Wres = 0; const float* Wclf = 0;
    for (int i = 0; i < n_in; ++i) {
        switch (in_sizes[i]) {
            case NB * NC * NT:   x    = (const float*)d_in[i]; break;
            case NRES * NC:      Win  = (const float*)d_in[i]; break;
            case NRES * NRES:    Wres = (const float*)d_in[i]; break;
            case NCLS * NRES:    Wclf = (const float*)d_in[i]; break;
        }
    }
    float* out = (float*)d_out;

    reservoir_persistent<<<NBLK, NTHR>>>(x, Win, Wres, Wclf, out);
}

// round 13
// speedup vs baseline: 1.0460x; 1.0460x over previous
#include <cuda_runtime.h>

#define NB   512
#define NC   16
#define NT   2000
#define NRES 1024
#define NCLS 10
#define NBLK 148
#define NTHR 512
#define ALPHA 0.9f

// Persistent cross-CTA state.
__device__ float g_s[2][NB * NRES];            // spikes, [b][j] (classifier)
__device__ unsigned g_mask[2][NB][32];         // spike bitmasks: bit i of word w = neuron 32w+i
__device__ float g_WresT[NRES * NRES];         // Wres^T, [k][j]
__device__ float g_xT[(size_t)NT * NB * NC];   // x^T: [t][b][c]
__device__ unsigned g_bar_count;
__device__ unsigned g_bar_gen;

static __device__ __forceinline__ unsigned ld_acq(const unsigned* p) {
    unsigned v;
    asm volatile("ld.acquire.gpu.global.u32 %0, [%1];" : "=r"(v) : "l"(p) : "memory");
    return v;
}
static __device__ __forceinline__ void st_rel(unsigned* p, unsigned v) {
    asm volatile("st.release.gpu.global.u32 [%0], %1;" :: "l"(p), "r"(v) : "memory");
}

// Grid-wide barrier; all 148 CTAs resident (1 per SM).
static __device__ __forceinline__ void grid_barrier() {
    __syncthreads();
    if (threadIdx.x == 0) {
        unsigned gen = ld_acq(&g_bar_gen);
        __threadfence();
        if (atomicAdd(&g_bar_count, 1u) == NBLK - 1u) {
            g_bar_count = 0u;
            __threadfence();
            st_rel(&g_bar_gen, gen + 1u);
        } else {
            while (ld_acq(&g_bar_gen) == gen) { }
        }
    }
    __syncthreads();
}

static __device__ __forceinline__ unsigned long long pack2(float lo, float hi) {
    unsigned long long r;
    asm("mov.b64 %0, {%1, %2};" : "=l"(r) : "f"(lo), "f"(hi));
    return r;
}
static __device__ __forceinline__ void unpack2(unsigned long long p, float& lo, float& hi) {
    asm("mov.b64 {%0, %1}, %2;" : "=f"(lo), "=f"(hi) : "l"(p));
}
// add.rn.f32x2: two independent rn fp32 adds — per-lane bit-identical to __fadd_rn.
static __device__ __forceinline__ unsigned long long add2(unsigned long long a,
                                                          unsigned long long b) {
    unsigned long long r;
    asm("add.rn.f32x2 %0, %1, %2;" : "=l"(r) : "l"(a), "l"(b));
    return r;
}

// cp.async 16B global->shared.
static __device__ __forceinline__ void cp16(unsigned dst_smem, const void* src) {
    asm volatile("cp.async.cg.shared.global [%0], [%1], 16;"
                 :: "r"(dst_smem), "l"(src) : "memory");
}
static __device__ __forceinline__ void cp_commit() {
    asm volatile("cp.async.commit_group;" ::: "memory");
}
static __device__ __forceinline__ void cp_wait0() {
    asm volatile("cp.async.wait_group 0;" ::: "memory");
}

__global__ __launch_bounds__(NTHR, 1) void reservoir_persistent(
    const float* __restrict__ x,     // (NB, NC, NT)
    const float* __restrict__ Win,   // (NRES, NC)
    const float* __restrict__ Wres,  // (NRES, NRES)
    const float* __restrict__ Wclf,  // (NCLS, NRES)
    float* __restrict__ out)         // [NB*NCLS | NB*NRES]
{
    const int blk = blockIdx.x;
    const int tid = threadIdx.x;

    __shared__ __align__(16) float Bs[2][32][64];   // WresT chunk, double-buffered
    __shared__ unsigned sMask[64][32];              // this b-tile's masks for step t
    __shared__ float sx[64][17];
    __shared__ float sWin[64][17];

    // ---- Phase 0 (all CTAs): one-time transposes + mask zero ----
    {
        const int g0 = blk * NTHR + tid;
        const int gs = NBLK * NTHR;
        for (int i = g0; i < NRES * NRES; i += gs) {
            int j = i >> 10, k = i & (NRES - 1);
            g_WresT[k * NRES + j] = Wres[i];
        }
        for (size_t i = g0; i < (size_t)NT * NB * NC; i += (size_t)gs) {
            int t = (int)(i >> 13);
            int r = (int)(i & 8191);
            int b = r >> 4, c = r & 15;
            g_xT[i] = x[((size_t)(b * NC + c)) * NT + t];
        }
        for (int i = g0; i < NB * 32; i += gs)
            ((unsigned*)g_mask[0])[i] = 0u;
    }

    if (blk < 128) {
        // ---------------- Reservoir path (512 threads, 16 warps) -------------
        const int b0 = (blk >> 4) * 64;
        const int j0 = (blk & 15) * 64;

        const int w    = tid >> 5;      // warp 0..15 -> rows w*4..w*4+3
        const int lane = tid & 31;      // lane -> cols lane*2, lane*2+1
        const int rl0 = w * 4;
        const int cl0 = lane * 2;

        // Staging decode for Bs chunk: 512 threads x 16B = 8KB.
        const int kq = tid >> 4;        // 0..31
        const int qq = tid & 15;        // 0..15
        const unsigned bs_u = (unsigned)__cvta_generic_to_shared(Bs);
        const unsigned bufBytes = 32 * 64 * 4;
        const unsigned dB = bs_u + (kq * 64 + qq * 4) * 4;

        // Zero step-0 float spikes (classifier reads them at t=1).
        {
#pragma unroll
            for (int i = 0; i < 4; i++)
                *(float2*)&g_s[0][(size_t)(b0 + rl0 + i) * NRES + j0 + cl0] =
                    make_float2(0.f, 0.f);
        }
        for (int e = tid; e < 64 * 16; e += NTHR) {
            int r = e >> 4, c = e & 15;
            sWin[r][c] = Win[(size_t)(j0 + r) * NC + c];
        }

        float v[8], cnt[8];
#pragma unroll
        for (int q = 0; q < 8; q++) { v[q] = 0.f; cnt[q] = 0.f; }

        grid_barrier();

        for (int t = 0; t < NT; ++t) {
            float* __restrict__ s_next = g_s[(t + 1) & 1];
            const int buf  = t & 1;
            const int nbuf = (t + 1) & 1;

            // Stage x_t tile + this b-tile's masks (visible after first chunk sync).
            {
                const float* xt = &g_xT[(size_t)t * (NB * NC) + (size_t)b0 * NC];
                for (int e = tid; e < 64 * 16; e += NTHR)
                    sx[e >> 4][e & 15] = xt[e];
                const unsigned* gm = &g_mask[buf][b0][0];
                for (int e = tid; e < 64 * 32; e += NTHR)
                    sMask[e >> 5][e & 31] = gm[e];
            }

            unsigned long long acc2[4];
#pragma unroll
            for (int i = 0; i < 4; i++) acc2[i] = pack2(0.f, 0.f);

            // Prologue: stage chunk 31 into buf 1.
            cp16(dB + bufBytes, &g_WresT[(size_t)(31 * 32 + kq) * NRES + j0 + qq * 4]);
            cp_commit();

            for (int kc = 31; kc >= 0; --kc) {
                cp_wait0();
                __syncthreads();

                if (kc > 0) {
                    cp16(dB + ((kc - 1) & 1) * bufBytes,
                         &g_WresT[(size_t)((kc - 1) * 32 + kq) * NRES + j0 + qq * 4]);
                    cp_commit();
                }

                const unsigned bbase = bs_u + (kc & 1) * bufBytes + cl0 * 4;
                // Sparse ordered accumulation: bits high->low = k descending.
                // add.rn per active k == fma(1,w,acc); skip == fma(0,w,acc). Bit-exact.
#pragma unroll
                for (int bb = 0; bb < 4; ++bb) {
                    unsigned m = sMask[rl0 + bb][kc];   // warp-uniform
                    unsigned long long a = acc2[bb];
                    while (m) {
                        int k = 31 - __clz(m);
                        m &= ~(1u << k);
                        unsigned long long w2;
                        asm("ld.shared.b64 %0, [%1];"
                            : "=l"(w2) : "r"(bbase + (unsigned)k * 256));
                        a = add2(a, w2);
                    }
                    acc2[bb] = a;
                }
            }

            __syncthreads();   // mainloop reads of Bs/sMask complete

            // Epilogue (frozen): vn = rn(fma(0.9, v, d_in) + d_rec)
#pragma unroll
            for (int i = 0; i < 4; i++) {
                const int rb = rl0 + i;
                float d0 = 0.f, d1 = 0.f;
#pragma unroll
                for (int c = 0; c < NC; c++) {
                    d0 = __fmaf_rn(sx[rb][c], sWin[cl0][c], d0);
                    d1 = __fmaf_rn(sx[rb][c], sWin[cl0 + 1][c], d1);
                }
                float r0, r1;
                unpack2(acc2[i], r0, r1);
                float vn0 = __fadd_rn(__fmaf_rn(ALPHA, v[i * 2 + 0], d0), r0);
                float vn1 = __fadd_rn(__fmaf_rn(ALPHA, v[i * 2 + 1], d1), r1);
                float s0 = (vn0 >= 1.0f) ? 1.0f : 0.0f;
                float s1 = (vn1 >= 1.0f) ? 1.0f : 0.0f;
                v[i * 2 + 0] = (vn0 >= 1.0f) ? 0.0f : vn0;
                v[i * 2 + 1] = (vn1 >= 1.0f) ? 0.0f : vn1;
                cnt[i * 2 + 0] += s0;
                cnt[i * 2 + 1] += s1;

                *(float2*)&s_next[(size_t)(b0 + rb) * NRES + j0 + cl0] =
                    make_float2(s0, s1);

                // Build next-step mask bits: bit (j mod 32) = spike(j).
                unsigned partial = ((s0 != 0.f) ? 1u : 0u) | ((s1 != 0.f) ? 2u : 0u);
                partial <<= (cl0 & 31);
                unsigned grp = (lane < 16) ? 0x0000FFFFu : 0xFFFF0000u;
                unsigned word = __reduce_or_sync(grp, partial);
                if ((lane & 15) == 0) {
                    g_mask[nbuf][b0 + rb][(j0 >> 5) + (lane >> 4)] = word;
                }
            }

            grid_barrier();
        }
        grid_barrier();   // classifier finishes step NT-1

#pragma unroll
        for (int i = 0; i < 4; i++) {
            *(float2*)&out[(size_t)NB * NCLS +
                           (size_t)(b0 + rl0 + i) * NRES + j0 + cl0] =
                make_float2(cnt[i * 2 + 0], cnt[i * 2 + 1]);
        }
    } else {
        // ---------------- Classifier path (tid<256 active; numerics frozen) --
        const bool active = tid < 256;
        const int idx = (blk - 128) * 256 + tid;
        const int b = idx / NCLS;
        const int m = idx % NCLS;
        float vc = 0.f, cc = 0.f;

        grid_barrier();

        for (int t = 0; t <= NT; ++t) {
            if (t >= 1 && active) {
                const float* __restrict__ s_prev = g_s[t & 1];
                const float* srow = &s_prev[(size_t)b * NRES];
                const float* wrow = &Wclf[(size_t)m * NRES];
                float tot = 0.f;
#pragma unroll
                for (int blkk = 0; blkk < 4; ++blkk) {
                    float a = 0.f;
#pragma unroll 8
                    for (int n = 0; n < 256; n += 4) {
                        int base = blkk * 256 + n;
                        float4 sv = __ldcg((const float4*)(srow + base));
                        float4 wv = *(const float4*)(wrow + base);
                        a = __fmaf_rn(sv.x, wv.x, a);
                        a = __fmaf_rn(sv.y, wv.y, a);
                        a = __fmaf_rn(sv.z, wv.z, a);
                        a = __fmaf_rn(sv.w, wv.w, a);
                    }
                    tot = __fadd_rn(tot, a);
                }
                float vn = __fmaf_rn(ALPHA, vc, tot);
                float s = (vn >= 1.0f) ? 1.0f : 0.0f;
                vc = (vn >= 1.0f) ? 0.0f : vn;
                cc += s;
            }
            grid_barrier();
        }
        if (active) out[idx] = cc;
    }
}

extern "C" void kernel_launch(void* const* d_in, const int* in_sizes, int n_in,
                              void* d_out, int out_size) {
    const float* x = 0; const float* Win = 0;
    const float* Wres = 0; const float* Wclf = 0;
    for (int i = 0; i < n_in; ++i) {
        switch (in_sizes[i]) {
            case NB * NC * NT:   x    = (const float*)d_in[i]; break;
            case NRES * NC:      Win  = (const float*)d_in[i]; break;
            case NRES * NRES:    Wres = (const float*)d_in[i]; break;
            case NCLS * NRES:    Wclf = (const float*)d_in[i]; break;
        }
    }
    float* out = (float*)d_out;

    reservoir_persistent<<<NBLK, NTHR>>>(x, Win, Wres, Wclf, out);
}

// round 14
// speedup vs baseline: 1.1984x; 1.1457x over previous
#include <cuda_runtime.h>

#define NB   512
#define NC   16
#define NT   2000
#define NRES 1024
#define NCLS 10
#define NBLK 148
#define NTHR 512
#define ALPHA 0.9f

// Persistent cross-CTA state.
__device__ float g_s[2][NB * NRES];            // spikes, [b][j] (classifier)
__device__ unsigned g_mask[2][NB][32];         // spike bitmask: bit i of word w = neuron 32w+i
__device__ float g_WresT[NRES * NRES];         // Wres^T, [k][j]
__device__ float g_xT[(size_t)NT * NB * NC];   // x^T: [t][b][c]
__device__ unsigned g_bar_count;
__device__ unsigned g_bar_gen;

static __device__ __forceinline__ unsigned ld_acq(const unsigned* p) {
    unsigned v;
    asm volatile("ld.acquire.gpu.global.u32 %0, [%1];" : "=r"(v) : "l"(p) : "memory");
    return v;
}
static __device__ __forceinline__ void st_rel(unsigned* p, unsigned v) {
    asm volatile("st.release.gpu.global.u32 [%0], %1;" :: "l"(p), "r"(v) : "memory");
}

// Grid-wide barrier; all 148 CTAs resident (1 per SM).
static __device__ __forceinline__ void grid_barrier() {
    __syncthreads();
    if (threadIdx.x == 0) {
        unsigned gen = ld_acq(&g_bar_gen);
        __threadfence();
        if (atomicAdd(&g_bar_count, 1u) == NBLK - 1u) {
            g_bar_count = 0u;
            __threadfence();
            st_rel(&g_bar_gen, gen + 1u);
        } else {
            while (ld_acq(&g_bar_gen) == gen) { }
        }
    }
    __syncthreads();
}

static __device__ __forceinline__ unsigned long long pack2(float lo, float hi) {
    unsigned long long r;
    asm("mov.b64 %0, {%1, %2};" : "=l"(r) : "f"(lo), "f"(hi));
    return r;
}
static __device__ __forceinline__ void unpack2(unsigned long long p, float& lo, float& hi) {
    asm("mov.b64 {%0, %1}, %2;" : "=f"(lo), "=f"(hi) : "l"(p));
}
// add.rn.f32x2: two independent rn fp32 adds — per-lane bit-identical to __fadd_rn.
static __device__ __forceinline__ unsigned long long add2(unsigned long long a,
                                                          unsigned long long b) {
    unsigned long long r;
    asm("add.rn.f32x2 %0, %1, %2;" : "=l"(r) : "l"(a), "l"(b));
    return r;
}

// cp.async 16B global->shared.
static __device__ __forceinline__ void cp16(unsigned dst_smem, const void* src) {
    asm volatile("cp.async.cg.shared.global [%0], [%1], 16;"
                 :: "r"(dst_smem), "l"(src) : "memory");
}
static __device__ __forceinline__ void cp_commit() {
    asm volatile("cp.async.commit_group;" ::: "memory");
}
static __device__ __forceinline__ void cp_wait0() {
    asm volatile("cp.async.wait_group 0;" ::: "memory");
}

__global__ __launch_bounds__(NTHR, 1) void reservoir_persistent(
    const float* __restrict__ x,     // (NB, NC, NT)
    const float* __restrict__ Win,   // (NRES, NC)
    const float* __restrict__ Wres,  // (NRES, NRES)
    const float* __restrict__ Wclf,  // (NCLS, NRES)
    float* __restrict__ out)         // [NB*NCLS | NB*NRES]
{
    const int blk = blockIdx.x;
    const int tid = threadIdx.x;

    __shared__ __align__(16) float Bs[2][32][128];  // WresT chunk (32k x 128j), dbl-buffered
    __shared__ unsigned sMask[32][32];              // masks for this b-tile, step t
    __shared__ float sx[32][17];
    __shared__ float sWin[128][17];

    // ---- Phase 0 (all CTAs): one-time transposes + mask zero ----
    {
        const int g0 = blk * NTHR + tid;
        const int gs = NBLK * NTHR;
        for (int i = g0; i < NRES * NRES; i += gs) {
            int j = i >> 10, k = i & (NRES - 1);
            g_WresT[k * NRES + j] = Wres[i];
        }
        for (size_t i = g0; i < (size_t)NT * NB * NC; i += (size_t)gs) {
            int t = (int)(i >> 13);
            int r = (int)(i & 8191);
            int b = r >> 4, c = r & 15;
            g_xT[i] = x[((size_t)(b * NC + c)) * NT + t];
        }
        for (int i = g0; i < NB * 32; i += gs)
            ((unsigned*)g_mask[0])[i] = 0u;
    }

    if (blk < 128) {
        // ------------- Reservoir path: CTA = 32 b x 128 j -------------------
        const int b0 = (blk >> 3) * 32;      // 16 b-tiles
        const int j0 = (blk & 7) * 128;      // 8 j-tiles

        const int w    = tid >> 5;           // warp 0..15 -> rows w*2, w*2+1
        const int lane = tid & 31;           // lane -> cols lane*4 .. lane*4+3
        const int rl0 = w * 2;
        const int cl0 = lane * 4;

        // Staging decode: chunk = 32k x 128j = 16KB; 512 threads x 2 cp16.
        const unsigned bs_u = (unsigned)__cvta_generic_to_shared(Bs);
        const unsigned bufBytes = 32 * 128 * 4;
        const int k0s = tid >> 5;            // slot0: k = tid/32,  q = tid%32
        const int q0s = tid & 31;
        const int k1s = (tid + 512) >> 5;    // slot1: k = 16 + tid/32
        const unsigned dB0 = bs_u + (unsigned)(k0s * 128 + q0s * 4) * 4;
        const unsigned dB1 = bs_u + (unsigned)(k1s * 128 + q0s * 4) * 4;

        // Zero step-0 float spikes.
        {
            float4 z = make_float4(0.f, 0.f, 0.f, 0.f);
#pragma unroll
            for (int i = 0; i < 2; i++)
                *(float4*)&g_s[0][(size_t)(b0 + rl0 + i) * NRES + j0 + cl0] = z;
        }
        for (int e = tid; e < 128 * 16; e += NTHR) {
            int r = e >> 4, c = e & 15;
            sWin[r][c] = Win[(size_t)(j0 + r) * NC + c];
        }

        float v[8], cnt[8];
#pragma unroll
        for (int q = 0; q < 8; q++) { v[q] = 0.f; cnt[q] = 0.f; }

        grid_barrier();

        for (int t = 0; t < NT; ++t) {
            float* __restrict__ s_next = g_s[(t + 1) & 1];
            const int buf  = t & 1;
            const int nbuf = (t + 1) & 1;

            // Stage x_t tile + this b-tile's masks (visible after first chunk sync).
            {
                const float* xt = &g_xT[(size_t)t * (NB * NC) + (size_t)b0 * NC];
                if (tid < 32 * 16) sx[tid >> 4][tid & 15] = xt[tid];
                const unsigned* gm = &g_mask[buf][b0][0];
                for (int e = tid; e < 32 * 32; e += NTHR)
                    sMask[e >> 5][e & 31] = gm[e];
            }

            // acc2[bb][h]: b row bb, j pair h (4 j total per lane).
            unsigned long long acc2[2][2];
#pragma unroll
            for (int i = 0; i < 2; i++) {
                acc2[i][0] = pack2(0.f, 0.f);
                acc2[i][1] = pack2(0.f, 0.f);
            }

            // Prologue: stage chunk 31 into buf 1.
            cp16(dB0 + bufBytes, &g_WresT[(size_t)(31 * 32 + k0s) * NRES + j0 + q0s * 4]);
            cp16(dB1 + bufBytes, &g_WresT[(size_t)(31 * 32 + k1s) * NRES + j0 + q0s * 4]);
            cp_commit();

            for (int kc = 31; kc >= 0; --kc) {
                cp_wait0();
                __syncthreads();

                if (kc > 0) {
                    const int kg = (kc - 1) * 32;
                    const unsigned off = ((kc - 1) & 1) * bufBytes;
                    cp16(dB0 + off, &g_WresT[(size_t)(kg + k0s) * NRES + j0 + q0s * 4]);
                    cp16(dB1 + off, &g_WresT[(size_t)(kg + k1s) * NRES + j0 + q0s * 4]);
                    cp_commit();
                }

                const unsigned bbase = bs_u + (kc & 1) * bufBytes + (unsigned)cl0 * 4;
                // Sparse ordered accumulation, bit-exact (add.rn per active k,
                // skip inactive; k descending within chunk; chunks descending).
#pragma unroll
                for (int bb = 0; bb < 2; ++bb) {
                    unsigned m = sMask[rl0 + bb][kc];   // warp-uniform
                    unsigned long long a0 = acc2[bb][0];
                    unsigned long long a1 = acc2[bb][1];
                    while (m) {
                        int k = 31 - __clz(m);
                        m &= ~(1u << k);
                        unsigned long long w01, w23;
                        asm("ld.shared.v2.u64 {%0, %1}, [%2];"
                            : "=l"(w01), "=l"(w23)
                            : "r"(bbase + (unsigned)k * 512));
                        a0 = add2(a0, w01);
                        a1 = add2(a1, w23);
                    }
                    acc2[bb][0] = a0;
                    acc2[bb][1] = a1;
                }
            }

            __syncthreads();   // mainloop reads of Bs/sMask complete

            // Epilogue (frozen): vn = rn(fma(0.9, v, d_in) + d_rec)
#pragma unroll
            for (int i = 0; i < 2; i++) {
                const int rb = rl0 + i;
                float d[4] = {0.f, 0.f, 0.f, 0.f};
#pragma unroll
                for (int c = 0; c < NC; c++) {
                    float xv = sx[rb][c];
#pragma unroll
                    for (int j = 0; j < 4; j++)
                        d[j] = __fmaf_rn(xv, sWin[cl0 + j][c], d[j]);
                }
                float r01[2], r23[2];
                unpack2(acc2[i][0], r01[0], r01[1]);
                unpack2(acc2[i][1], r23[0], r23[1]);
                float rr[4] = {r01[0], r01[1], r23[0], r23[1]};
                float sp[4];
                unsigned bits = 0;
#pragma unroll
                for (int j = 0; j < 4; j++) {
                    float vn = __fadd_rn(__fmaf_rn(ALPHA, v[i * 4 + j], d[j]), rr[j]);
                    float s = (vn >= 1.0f) ? 1.0f : 0.0f;
                    v[i * 4 + j] = (vn >= 1.0f) ? 0.0f : vn;
                    cnt[i * 4 + j] += s;
                    sp[j] = s;
                    bits |= (s != 0.f) ? (1u << j) : 0u;
                }
                *(float4*)&s_next[(size_t)(b0 + rb) * NRES + j0 + cl0] =
                    make_float4(sp[0], sp[1], sp[2], sp[3]);

                // Next-step mask: word = 32 j = 8 lanes (4 bits each).
                unsigned partial = bits << (cl0 & 31);
                unsigned grp = 0xFFu << ((lane >> 3) << 3);
                unsigned word = __reduce_or_sync(grp, partial);
                if ((lane & 7) == 0)
                    g_mask[nbuf][b0 + rb][(j0 >> 5) + (lane >> 3)] = word;
            }

            grid_barrier();
        }
        grid_barrier();   // classifier finishes step NT-1

#pragma unroll
        for (int i = 0; i < 2; i++) {
            *(float4*)&out[(size_t)NB * NCLS +
                           (size_t)(b0 + rl0 + i) * NRES + j0 + cl0] =
                make_float4(cnt[i * 4 + 0], cnt[i * 4 + 1],
                            cnt[i * 4 + 2], cnt[i * 4 + 3]);
        }
    } else {
        // ---------------- Classifier path (tid<256 active; numerics frozen) --
        const bool active = tid < 256;
        const int idx = (blk - 128) * 256 + tid;
        const int b = idx / NCLS;
        const int m = idx % NCLS;
        float vc = 0.f, cc = 0.f;

        grid_barrier();

        for (int t = 0; t <= NT; ++t) {
            if (t >= 1 && active) {
                const float* __restrict__ s_prev = g_s[t & 1];
                const float* srow = &s_prev[(size_t)b * NRES];
                const float* wrow = &Wclf[(size_t)m * NRES];
                float tot = 0.f;
#pragma unroll
                for (int blkk = 0; blkk < 4; ++blkk) {
                    float a = 0.f;
#pragma unroll 8
                    for (int n = 0; n < 256; n += 4) {
                        int base = blkk * 256 + n;
                        float4 sv = __ldcg((const float4*)(srow + base));
                        float4 wv = *(const float4*)(wrow + base);
                        a = __fmaf_rn(sv.x, wv.x, a);
                        a = __fmaf_rn(sv.y, wv.y, a);
                        a = __fmaf_rn(sv.z, wv.z, a);
                        a = __fmaf_rn(sv.w, wv.w, a);
                    }
                    tot = __fadd_rn(tot, a);
                }
                float vn = __fmaf_rn(ALPHA, vc, tot);
                float s = (vn >= 1.0f) ? 1.0f : 0.0f;
                vc = (vn >= 1.0f) ? 0.0f : vn;
                cc += s;
            }
            grid_barrier();
        }
        if (active) out[idx] = cc;
    }
}

extern "C" void kernel_launch(void* const* d_in, const int* in_sizes, int n_in,
                              void* d_out, int out_size) {
    const float* x = 0; const float* Win = 0;
    const float* Wres = 0; const float* Wclf = 0;
    for (int i = 0; i < n_in; ++i) {
        switch (in_sizes[i]) {
            case NB * NC * NT:   x    = (const float*)d_in[i]; break;
            case NRES * NC:      Win  = (const float*)d_in[i]; break;
            case NRES * NRES:    Wres = (const float*)d_in[i]; break;
            case NCLS * NRES:    Wclf = (const float*)d_in[i]; break;
        }
    }
    float* out = (float*)d_out;

    reservoir_persistent<<<NBLK, NTHR>>>(x, Win, Wres, Wclf, out);
}